// round 2
// baseline (speedup 1.0000x reference)
#include <cuda_runtime.h>
#include <math_constants.h>

#define N_SEG 128
#define P     512
#define D     64
#define KT    15
#define NC    8

__device__ float g_partials[N_SEG];
__device__ int   g_ticket = 0;   // reset to 0 by the last block every launch

__global__ __launch_bounds__(512, 1)
void lmnn_fused_kernel(const float* __restrict__ center,
                       const float* __restrict__ outputs,
                       const int*   __restrict__ labels,
                       float*       __restrict__ out)
{
    __shared__ float sdist[P];
    __shared__ int   slab[P];
    __shared__ float sS[NC];
    __shared__ float sM[NC];
    __shared__ int   sCnt[NC];
    __shared__ float sred[16];
    __shared__ int   s_last;

    const int i = blockIdx.x;
    const int t = threadIdx.x;
    const int w = t >> 5;
    const int lane = t & 31;

    // ---- load labels (one per thread) ----
    slab[t] = labels[i * P + t];

    // ---- Phase 1: dist_c[j] = ||outputs[i,j,:] - center[i,:]||^2 ----
    // 8192 float4s per segment; thread t handles g = t + 512*s.
    // (t & 15) is the d-offset of the float4 (constant across s), so each
    // thread needs exactly one float4 of the center.
    const float4* __restrict__ out4 = (const float4*)(outputs + (size_t)i * P * D);
    const float4  c4 = ((const float4*)(center + i * D))[t & 15];

    // Front-batch ALL loads for max MLP (hide ~577cyc DRAM latency once).
    float4 v[16];
    #pragma unroll
    for (int s = 0; s < 16; ++s)
        v[s] = out4[t + 512 * s];

    #pragma unroll
    for (int s = 0; s < 16; ++s) {
        const int g = t + 512 * s;
        float dx = v[s].x - c4.x;
        float dy = v[s].y - c4.y;
        float dz = v[s].z - c4.z;
        float dw = v[s].w - c4.w;
        float part = dx * dx + dy * dy + dz * dz + dw * dw;
        // reduce groups of 16 lanes (one point = 16 consecutive float4s)
        part += __shfl_down_sync(0xffffffffu, part, 8);
        part += __shfl_down_sync(0xffffffffu, part, 4);
        part += __shfl_down_sync(0xffffffffu, part, 2);
        part += __shfl_down_sync(0xffffffffu, part, 1);
        if ((t & 15) == 0) sdist[g >> 4] = part;
    }
    __syncthreads();

    // ---- Phase 2: per-class stats. Warp w (< 8) handles class c = w. ----
    // top_k over -dd has all finite entries equal (dist_c[j] broadcast along
    // k), so jax tie-breaking selects the FIRST KT same-class indices.
    if (w < NC) {
        const int c = w;
        float S  = 0.0f;
        float Mx = -CUDART_INF_F;
        int   cnt = 0;
        int   taken = 0;
        #pragma unroll 4
        for (int base = 0; base < P; base += 32) {
            const bool m = (slab[base + lane] == c);
            const unsigned mask = __ballot_sync(0xffffffffu, m);
            const int pc = __popc(mask);
            const int need = KT - taken;
            if (need > 0) {
                const int rank = __popc(mask & ((1u << lane) - 1u));
                if (m && rank < need) {
                    const float dv = sdist[base + lane];
                    S += dv;
                    Mx = fmaxf(Mx, dv);
                }
                taken += (pc < need) ? pc : need;
            }
            cnt += pc;
        }
        #pragma unroll
        for (int off = 16; off > 0; off >>= 1) {
            S += __shfl_xor_sync(0xffffffffu, S, off);
            Mx = fmaxf(Mx, __shfl_xor_sync(0xffffffffu, Mx, off));
        }
        if (lane == 0) { sS[c] = S; sM[c] = Mx; sCnt[c] = cnt; }
    }
    __syncthreads();

    // ---- Phase 3: margin_seg = 1 + max over present classes of M_c ----
    float ms = -CUDART_INF_F;
    #pragma unroll
    for (int c = 0; c < NC; ++c)
        if (sCnt[c] > 0) ms = fmaxf(ms, sM[c]);
    ms += 1.0f;

    // ---- Phase 4: push term per point j = t ----
    const int   cj = slab[t];
    const float dv = sdist[t];
    float term = 0.0f;
    if (dv < ms) {
        term = (float)(P - sCnt[cj]) * fmaxf(1.0f + sM[cj] - dv, 0.0f);
    }
    #pragma unroll
    for (int off = 16; off > 0; off >>= 1)
        term += __shfl_xor_sync(0xffffffffu, term, off);
    if (lane == 0) sred[w] = term;
    __syncthreads();

    // ---- Phase 5: per-segment partial, then last-block final reduce ----
    if (t == 0) {
        float v16 = 0.0f;
        #pragma unroll
        for (int k = 0; k < 16; ++k) v16 += sred[k];
        float pull = 0.0f;
        #pragma unroll
        for (int c = 0; c < NC; ++c)
            pull += (float)sCnt[c] * sS[c];
        g_partials[i] = pull + v16;
        __threadfence();
        int prev = atomicAdd(&g_ticket, 1);
        s_last = (prev == N_SEG - 1) ? 1 : 0;
    }
    __syncthreads();

    if (s_last) {
        // Last block: deterministically reduce the 128 partials (warp 0).
        if (w == 0) {
            float a = g_partials[lane];
            float b = g_partials[lane + 32];
            float c2 = g_partials[lane + 64];
            float d2 = g_partials[lane + 96];
            float vsum = (a + b) + (c2 + d2);
            #pragma unroll
            for (int off = 16; off > 0; off >>= 1)
                vsum += __shfl_xor_sync(0xffffffffu, vsum, off);
            if (lane == 0) {
                out[0] = vsum * (1.0f / (float)(N_SEG * P));
                g_ticket = 0;   // reset for next (graph-replayed) launch
            }
        }
    }
}

extern "C" void kernel_launch(void* const* d_in, const int* in_sizes, int n_in,
                              void* d_out, int out_size)
{
    const float* center  = (const float*)d_in[0];  // (128, 64)    f32
    const float* outputs = (const float*)d_in[1];  // (128,512,64) f32
    const int*   labels  = (const int*)d_in[2];    // (128, 512)   i32

    lmnn_fused_kernel<<<N_SEG, 512>>>(center, outputs, labels, (float*)d_out);
}

// round 3
// speedup vs baseline: 1.0239x; 1.0239x over previous
#include <cuda_runtime.h>
#include <math_constants.h>

#define N_SEG 128
#define P     512
#define D     64
#define KT    15
#define NC    8
#define NT    1024   // threads per block
#define NW    (NT/32)

__device__ float g_partials[N_SEG];
__device__ int   g_ticket = 0;   // reset by last block each launch

__global__ __launch_bounds__(NT, 1)
void lmnn_fused_kernel(const float* __restrict__ center,
                       const float* __restrict__ outputs,
                       const int*   __restrict__ labels,
                       float*       __restrict__ out)
{
    __shared__ float sdist[P];
    __shared__ int   slab[P];
    __shared__ float sS[NC];
    __shared__ float sM[NC];
    __shared__ int   sCnt[NC];
    __shared__ float sred[NW];
    __shared__ int   s_last;

    const int i = blockIdx.x;
    const int t = threadIdx.x;
    const int w = t >> 5;
    const int lane = t & 31;

    // ---- labels into shared (first 512 threads) ----
    if (t < P) slab[t] = labels[i * P + t];

    // ---- Phase 1: dist_c[j] = ||outputs[i,j,:] - center[i,:]||^2 ----
    // 8192 float4s per segment; thread t handles g = t + 1024*s, s<8.
    // (t & 15) is the d-offset of the float4 (constant across s).
    const float4* __restrict__ out4 = (const float4*)(outputs + (size_t)i * P * D);
    const float4  c4 = ((const float4*)(center + i * D))[t & 15];

    // Front-batch all 8 loads (streaming: data is read exactly once).
    float4 v[8];
    #pragma unroll
    for (int s = 0; s < 8; ++s)
        v[s] = __ldcs(&out4[t + NT * s]);

    #pragma unroll
    for (int s = 0; s < 8; ++s) {
        const int g = t + NT * s;
        float dx = v[s].x - c4.x;
        float dy = v[s].y - c4.y;
        float dz = v[s].z - c4.z;
        float dw = v[s].w - c4.w;
        float part = dx * dx + dy * dy + dz * dz + dw * dw;
        // 16 lanes = one point (16 consecutive float4s)
        part += __shfl_down_sync(0xffffffffu, part, 8);
        part += __shfl_down_sync(0xffffffffu, part, 4);
        part += __shfl_down_sync(0xffffffffu, part, 2);
        part += __shfl_down_sync(0xffffffffu, part, 1);
        if ((t & 15) == 0) sdist[g >> 4] = part;
    }
    __syncthreads();

    // ---- Phase 2: per-class stats; warp w < 8 handles class c = w. ----
    // top_k over -dd has all finite entries equal (dist_c[j] broadcast along
    // k), so jax tie-breaking selects the FIRST KT same-class indices.
    if (w < NC) {
        const int c = w;
        float S  = 0.0f;
        float Mx = -CUDART_INF_F;
        int   cnt = 0;
        int   taken = 0;
        #pragma unroll 4
        for (int base = 0; base < P; base += 32) {
            const bool m = (slab[base + lane] == c);
            const unsigned mask = __ballot_sync(0xffffffffu, m);
            const int pc = __popc(mask);
            const int need = KT - taken;
            if (need > 0) {
                const int rank = __popc(mask & ((1u << lane) - 1u));
                if (m && rank < need) {
                    const float dv = sdist[base + lane];
                    S += dv;
                    Mx = fmaxf(Mx, dv);
                }
                taken += (pc < need) ? pc : need;
            }
            cnt += pc;
        }
        #pragma unroll
        for (int off = 16; off > 0; off >>= 1) {
            S += __shfl_xor_sync(0xffffffffu, S, off);
            Mx = fmaxf(Mx, __shfl_xor_sync(0xffffffffu, Mx, off));
        }
        if (lane == 0) { sS[c] = S; sM[c] = Mx; sCnt[c] = cnt; }
    }
    __syncthreads();

    // ---- Phase 3: margin_seg = 1 + max over present classes ----
    float ms = -CUDART_INF_F;
    #pragma unroll
    for (int c = 0; c < NC; ++c)
        if (sCnt[c] > 0) ms = fmaxf(ms, sM[c]);
    ms += 1.0f;

    // ---- Phase 4: push term per point (first 512 threads) ----
    float term = 0.0f;
    if (t < P) {
        const int   cj = slab[t];
        const float dv = sdist[t];
        if (dv < ms)
            term = (float)(P - sCnt[cj]) * fmaxf(1.0f + sM[cj] - dv, 0.0f);
    }
    #pragma unroll
    for (int off = 16; off > 0; off >>= 1)
        term += __shfl_xor_sync(0xffffffffu, term, off);
    if (lane == 0) sred[w] = term;
    __syncthreads();

    // ---- Phase 5: per-segment partial + last-block finish ----
    if (t == 0) {
        float v32 = 0.0f;
        #pragma unroll
        for (int k = 0; k < NW; ++k) v32 += sred[k];
        float pull = 0.0f;
        #pragma unroll
        for (int c = 0; c < NC; ++c)
            pull += (float)sCnt[c] * sS[c];
        g_partials[i] = pull + v32;
        __threadfence();
        int prev = atomicAdd(&g_ticket, 1);
        s_last = (prev == N_SEG - 1) ? 1 : 0;
    }
    __syncthreads();

    if (s_last && w == 0) {
        float a  = g_partials[lane];
        float b  = g_partials[lane + 32];
        float c2 = g_partials[lane + 64];
        float d2 = g_partials[lane + 96];
        float vsum = (a + b) + (c2 + d2);
        #pragma unroll
        for (int off = 16; off > 0; off >>= 1)
            vsum += __shfl_xor_sync(0xffffffffu, vsum, off);
        if (lane == 0) {
            out[0] = vsum * (1.0f / (float)(N_SEG * P));
            g_ticket = 0;   // reset for next graph replay
        }
    }
}

extern "C" void kernel_launch(void* const* d_in, const int* in_sizes, int n_in,
                              void* d_out, int out_size)
{
    const float* center  = (const float*)d_in[0];  // (128, 64)    f32
    const float* outputs = (const float*)d_in[1];  // (128,512,64) f32
    const int*   labels  = (const int*)d_in[2];    // (128, 512)   i32

    lmnn_fused_kernel<<<N_SEG, NT>>>(center, outputs, labels, (float*)d_out);
}